// round 1
// baseline (speedup 1.0000x reference)
#include <cuda_runtime.h>
#include <math.h>

#define cB 8
#define cS 256
#define cH 768
#define cNH 4
#define cDH 192
#define cV 32000
#define cFF 3072
#define cSTEPS 32
#define BSH (cB*cS*cH)

// ---------------- static scratch (no dynamic allocation allowed) ----------------
static __device__ float g_bias[cB*cS];
static __device__ float g_Kc[3*BSH];      // K of hidden_states for ctx, cross0, cross1
static __device__ float g_Vc[3*BSH];      // V of hidden_states for ctx, cross0, cross1
static __device__ float g_xctx[cB*cSTEPS*cH];     // cached ctx-attn outputs per position
static __device__ float g_qkv0[cB*cSTEPS*3*cH];   // cached layer-0 self-attn QKV per position
static __device__ float g_dec[cB*cH];
static __device__ float g_qnew[cB*cH];
static __device__ float g_raw1[cB*cH];
static __device__ float g_h8[cB*cH];
static __device__ float g_x8[cB*cH];
static __device__ float g_ff8[cB*cFF];
static __device__ float g_x1[cB*cSTEPS*cH];
static __device__ float g_hb[cB*cSTEPS*cH];
static __device__ float g_qkv1[cB*cSTEPS*3*cH];
static __device__ float g_qb[cB*cSTEPS*cH];
static __device__ float g_rawb[cB*cSTEPS*cH];
static __device__ float g_ffb[cB*cSTEPS*cFF];

// ---------------- generic SGEMM: C[M,N] = A[M,K] @ W[N,K]^T + bias ----------------
// BM=64 BN=64 BK=16, 256 threads, 4x4 micro-tile, smem transposed for float4 reads.
__global__ __launch_bounds__(256)
void gemm_k(const float* __restrict__ A, int lda,
            const float* __restrict__ W,
            const float* __restrict__ bias,
            float* __restrict__ C, int ldc,
            int M, int N, int K, int relu)
{
    __shared__ float As[16][68];
    __shared__ float Ws[16][68];
    const int tid = threadIdx.x;
    const int bm = blockIdx.y * 64;
    const int bn = blockIdx.x * 64;
    const int m0 = (tid >> 4) * 4;
    const int n0 = (tid & 15) * 4;
    float acc[4][4] = {};
    for (int k0 = 0; k0 < K; k0 += 16) {
        #pragma unroll
        for (int i = 0; i < 4; i++) {
            int idx = tid + i * 256;        // 0..1023
            int r = idx >> 4;               // row within tile (0..63)
            int c = idx & 15;               // k within tile
            int gm = bm + r;
            As[c][r] = (gm < M) ? A[(size_t)gm * lda + k0 + c] : 0.f;
            Ws[c][r] = W[(size_t)(bn + r) * K + k0 + c];
        }
        __syncthreads();
        #pragma unroll
        for (int kk = 0; kk < 16; kk++) {
            float4 a = *(const float4*)(&As[kk][m0]);
            float4 w = *(const float4*)(&Ws[kk][n0]);
            float av[4] = {a.x, a.y, a.z, a.w};
            float wv[4] = {w.x, w.y, w.z, w.w};
            #pragma unroll
            for (int i = 0; i < 4; i++)
                #pragma unroll
                for (int j = 0; j < 4; j++)
                    acc[i][j] += av[i] * wv[j];
        }
        __syncthreads();
    }
    #pragma unroll
    for (int i = 0; i < 4; i++) {
        int gm = bm + m0 + i;
        if (gm < M) {
            #pragma unroll
            for (int j = 0; j < 4; j++) {
                int gn = bn + n0 + j;
                float v = acc[i][j] + bias[gn];
                if (relu) v = fmaxf(v, 0.f);
                C[(size_t)gm * ldc + gn] = v;
            }
        }
    }
}

// ---------------- cross attention (encoder K/V, 256 keys, with key bias) ----------------
// Q rows: (b*nq + i), out rows same. grid: (B*NH, ceil(nq/8)), 256 threads.
__global__ __launch_bounds__(256)
void cross_attn_k(const float* __restrict__ Q, int nq,
                  const float* __restrict__ Kp,
                  const float* __restrict__ Vp,
                  const float* __restrict__ bias,
                  float* __restrict__ Out)
{
    __shared__ float qs[8][193];
    __shared__ float ks[32][193];
    __shared__ float sc[8][256];
    const int bh = blockIdx.x;
    const int b = bh / cNH, h = bh % cNH;
    const int i0 = blockIdx.y * 8;
    const int ni = min(8, nq - i0);
    const int tid = threadIdx.x;
    const float scale = 0.07216878364870322f; // 1/sqrt(192)

    for (int idx = tid; idx < ni * cDH; idx += 256) {
        int i = idx / cDH, d = idx % cDH;
        qs[i][d] = Q[(size_t)(b * nq + i0 + i) * cH + h * cDH + d];
    }
    __syncthreads();

    for (int jt = 0; jt < cS; jt += 32) {
        for (int idx = tid; idx < 32 * cDH; idx += 256) {
            int j = idx / cDH, d = idx % cDH;
            ks[j][d] = Kp[(size_t)(b * cS + jt + j) * cH + h * cDH + d];
        }
        __syncthreads();
        {
            int i = tid >> 5, j = tid & 31;
            if (i < ni) {
                float s = 0.f;
                #pragma unroll 8
                for (int d = 0; d < cDH; d++) s += qs[i][d] * ks[j][d];
                sc[i][jt + j] = s * scale + bias[b * cS + jt + j];
            }
        }
        __syncthreads();
    }

    // softmax, one warp per query row
    {
        int w = tid >> 5, lane = tid & 31;
        if (w < ni) {
            float mx = -3.4e38f;
            for (int j = lane; j < cS; j += 32) mx = fmaxf(mx, sc[w][j]);
            #pragma unroll
            for (int o = 16; o; o >>= 1) mx = fmaxf(mx, __shfl_xor_sync(0xffffffffu, mx, o));
            float sum = 0.f;
            for (int j = lane; j < cS; j += 32) {
                float e = expf(sc[w][j] - mx);
                sc[w][j] = e; sum += e;
            }
            #pragma unroll
            for (int o = 16; o; o >>= 1) sum += __shfl_xor_sync(0xffffffffu, sum, o);
            float inv = 1.f / sum;
            for (int j = lane; j < cS; j += 32) sc[w][j] *= inv;
        }
    }
    __syncthreads();

    // AV with V tiles in smem, register accumulators
    {
        int i = tid >> 5, lane = tid & 31;
        float oacc[6] = {0.f, 0.f, 0.f, 0.f, 0.f, 0.f};
        for (int jt = 0; jt < cS; jt += 32) {
            for (int idx = tid; idx < 32 * cDH; idx += 256) {
                int j = idx / cDH, d = idx % cDH;
                ks[j][d] = Vp[(size_t)(b * cS + jt + j) * cH + h * cDH + d];
            }
            __syncthreads();
            if (i < ni) {
                float p = sc[i][jt + lane];
                #pragma unroll 8
                for (int j = 0; j < 32; j++) {
                    float pj = __shfl_sync(0xffffffffu, p, j);
                    #pragma unroll
                    for (int k = 0; k < 6; k++)
                        oacc[k] += pj * ks[j][lane + 32 * k];
                }
            }
            __syncthreads();
        }
        if (i < ni) {
            #pragma unroll
            for (int k = 0; k < 6; k++)
                Out[(size_t)(b * nq + i0 + i) * cH + h * cDH + lane + 32 * k] = oacc[k];
        }
    }
}

// ---------------- self attention over decoder tokens (L<=32, no bias) ----------------
// QKV rows: (b*rs + l)*(3H) with q|k|v packed. grid: B*NH, 256 threads.
__global__ __launch_bounds__(256)
void self_attn_k(const float* __restrict__ QKV, int rs, int L,
                 float* __restrict__ Out, int lastonly)
{
    __shared__ float ks[32][193];
    __shared__ float sc[32][33];
    const int b = blockIdx.x / cNH, h = blockIdx.x % cNH;
    const int tid = threadIdx.x;
    const float scale = 0.07216878364870322f;

    for (int idx = tid; idx < L * cDH; idx += 256) {
        int j = idx / cDH, d = idx % cDH;
        ks[j][d] = QKV[(size_t)(b * rs + j) * (3 * cH) + cH + h * cDH + d];
    }
    __syncthreads();

    const int i_lo = lastonly ? (L - 1) : 0;
    const int nq2 = lastonly ? 1 : L;
    for (int idx = tid; idx < nq2 * L; idx += 256) {
        int r = idx / L, j = idx % L;
        const float* q = QKV + (size_t)(b * rs + i_lo + r) * (3 * cH) + h * cDH;
        float s = 0.f;
        #pragma unroll 8
        for (int d = 0; d < cDH; d++) s += q[d] * ks[j][d];
        sc[r][j] = s * scale;
    }
    __syncthreads();

    {
        int w = tid >> 5, lane = tid & 31;
        for (int r = w; r < nq2; r += 8) {
            float x = (lane < L) ? sc[r][lane] : -3.4e38f;
            float mx = x;
            #pragma unroll
            for (int o = 16; o; o >>= 1) mx = fmaxf(mx, __shfl_xor_sync(0xffffffffu, mx, o));
            float e = (lane < L) ? expf(x - mx) : 0.f;
            float sum = e;
            #pragma unroll
            for (int o = 16; o; o >>= 1) sum += __shfl_xor_sync(0xffffffffu, sum, o);
            if (lane < L) sc[r][lane] = e / sum;
        }
    }
    __syncthreads();

    // load V
    for (int idx = tid; idx < L * cDH; idx += 256) {
        int j = idx / cDH, d = idx % cDH;
        ks[j][d] = QKV[(size_t)(b * rs + j) * (3 * cH) + 2 * cH + h * cDH + d];
    }
    __syncthreads();

    if (lastonly) {
        if (tid < cDH) {
            float acc = 0.f;
            for (int j = 0; j < L; j++) acc += sc[0][j] * ks[j][tid];
            Out[(size_t)b * cH + h * cDH + tid] = acc;
        }
    } else {
        int w = tid >> 5, lane = tid & 31;
        for (int r = w; r < L; r += 8) {
            #pragma unroll
            for (int k = 0; k < 6; k++) {
                int d = lane + 32 * k;
                float acc = 0.f;
                for (int j = 0; j < L; j++) acc += sc[r][j] * ks[j][d];
                Out[(size_t)(b * L + r) * cH + h * cDH + d] = acc;
            }
        }
    }
}

// ---------------- fused residual + LayerNorm ----------------
// row m: b = m/Lq, l = m%Lq; row offsets use per-b strides sx/sh/sy (in rows of H).
__global__ __launch_bounds__(256)
void add_ln_k(const float* __restrict__ X, int sx,
              const float* __restrict__ Hh, int sh,
              float* __restrict__ Y, int sy, int Lq,
              const float* __restrict__ gamma,
              const float* __restrict__ beta)
{
    const int m = blockIdx.x;
    const int bb = m / Lq, l = m - bb * Lq;
    const float* x = X + ((size_t)bb * sx + l) * cH;
    const float* hh = Hh + ((size_t)bb * sh + l) * cH;
    float* y = Y + ((size_t)bb * sy + l) * cH;
    const int tid = threadIdx.x;
    __shared__ float red[8];

    float v0 = x[tid] + hh[tid];
    float v1 = x[tid + 256] + hh[tid + 256];
    float v2 = x[tid + 512] + hh[tid + 512];
    float s = v0 + v1 + v2;
    #pragma unroll
    for (int o = 16; o; o >>= 1) s += __shfl_xor_sync(0xffffffffu, s, o);
    if ((tid & 31) == 0) red[tid >> 5] = s;
    __syncthreads();
    float tot = 0.f;
    #pragma unroll
    for (int k = 0; k < 8; k++) tot += red[k];
    float mean = tot * (1.f / 768.f);
    float d0 = v0 - mean, d1 = v1 - mean, d2 = v2 - mean;
    float q = d0 * d0 + d1 * d1 + d2 * d2;
    #pragma unroll
    for (int o = 16; o; o >>= 1) q += __shfl_xor_sync(0xffffffffu, q, o);
    __syncthreads();
    if ((tid & 31) == 0) red[tid >> 5] = q;
    __syncthreads();
    float vq = 0.f;
    #pragma unroll
    for (int k = 0; k < 8; k++) vq += red[k];
    float inv = rsqrtf(vq * (1.f / 768.f) + 1e-5f);
    y[tid]       = d0 * inv * gamma[tid]       + beta[tid];
    y[tid + 256] = d1 * inv * gamma[tid + 256] + beta[tid + 256];
    y[tid + 512] = d2 * inv * gamma[tid + 512] + beta[tid + 512];
}

// ---------------- misc small kernels ----------------
__global__ void bias_k(const int* __restrict__ mask, float* __restrict__ out)
{
    int i = blockIdx.x * 256 + threadIdx.x;
    if (i < cB * cS) out[i] = (mask[i] == 0) ? -1e9f : 0.f;
}

__global__ void embed0_k(const int* __restrict__ sent, const float* __restrict__ temb,
                         float* __restrict__ dec)
{
    int b = blockIdx.x;
    int s = sent[b];
    for (int d = threadIdx.x; d < cH; d += 256)
        dec[b * cH + d] = temb[s * cH + d];
}

__global__ __launch_bounds__(256)
void argmax_embed_k(const float* __restrict__ logits, int ldl,
                    const float* __restrict__ tok_w,
                    const float* __restrict__ tok_b,
                    float* __restrict__ dec)
{
    const int b = blockIdx.x;
    const float* row = logits + (size_t)b * ldl;
    const int tid = threadIdx.x;
    float best = -3.4e38f;
    int bidx = 0x7fffffff;
    for (int v = tid; v < cV; v += 256) {
        float x = row[v];
        if (x > best || (x == best && v < bidx)) { best = x; bidx = v; }
    }
    __shared__ float sv[256];
    __shared__ int si[256];
    sv[tid] = best; si[tid] = bidx;
    __syncthreads();
    for (int s = 128; s; s >>= 1) {
        if (tid < s) {
            if (sv[tid + s] > sv[tid] || (sv[tid + s] == sv[tid] && si[tid + s] < si[tid])) {
                sv[tid] = sv[tid + s]; si[tid] = si[tid + s];
            }
        }
        __syncthreads();
    }
    int id = si[0];
    for (int d = tid; d < cH; d += 256)
        dec[b * cH + d] = tok_w[(size_t)d * cV + id] + tok_b[d];
}

// ---------------- host orchestration ----------------
extern "C" void kernel_launch(void* const* d_in, const int* in_sizes, int n_in,
                              void* d_out, int out_size)
{
    (void)in_sizes; (void)n_in; (void)out_size;
    const float* hs          = (const float*)d_in[0];
    const int*   sent        = (const int*)d_in[1];
    const int*   amask       = (const int*)d_in[2];
    const float* temb        = (const float*)d_in[5];
    const float* ctx_in_w    = (const float*)d_in[6];
    const float* ctx_in_b    = (const float*)d_in[7];
    const float* ctx_out_w   = (const float*)d_in[8];
    const float* ctx_out_b   = (const float*)d_in[9];
    const float* self_in_w   = (const float*)d_in[10];
    const float* self_in_b   = (const float*)d_in[11];
    const float* self_out_w  = (const float*)d_in[12];
    const float* self_out_b  = (const float*)d_in[13];
    const float* cross_in_w  = (const float*)d_in[14];
    const float* cross_in_b  = (const float*)d_in[15];
    const float* cross_out_w = (const float*)d_in[16];
    const float* cross_out_b = (const float*)d_in[17];
    const float* ff1_w       = (const float*)d_in[18];
    const float* ff1_b       = (const float*)d_in[19];
    const float* ff2_w       = (const float*)d_in[20];
    const float* ff2_b       = (const float*)d_in[21];
    const float* norm_g      = (const float*)d_in[22];
    const float* norm_b      = (const float*)d_in[23];
    const float* out_w       = (const float*)d_in[24];
    const float* out_b       = (const float*)d_in[25];
    const float* tok_w       = (const float*)d_in[26];
    const float* tok_b       = (const float*)d_in[27];
    float* out = (float*)d_out;

    float *pBias, *pK, *pV, *pXctx, *pQkv0, *pDec, *pQnew, *pRaw1, *pH8, *pX8, *pFF8;
    float *pX1, *pHb, *pQkv1, *pQb, *pRawb, *pFFb;
    cudaGetSymbolAddress((void**)&pBias, g_bias);
    cudaGetSymbolAddress((void**)&pK,    g_Kc);
    cudaGetSymbolAddress((void**)&pV,    g_Vc);
    cudaGetSymbolAddress((void**)&pXctx, g_xctx);
    cudaGetSymbolAddress((void**)&pQkv0, g_qkv0);
    cudaGetSymbolAddress((void**)&pDec,  g_dec);
    cudaGetSymbolAddress((void**)&pQnew, g_qnew);
    cudaGetSymbolAddress((void**)&pRaw1, g_raw1);
    cudaGetSymbolAddress((void**)&pH8,   g_h8);
    cudaGetSymbolAddress((void**)&pX8,   g_x8);
    cudaGetSymbolAddress((void**)&pFF8,  g_ff8);
    cudaGetSymbolAddress((void**)&pX1,   g_x1);
    cudaGetSymbolAddress((void**)&pHb,   g_hb);
    cudaGetSymbolAddress((void**)&pQkv1, g_qkv1);
    cudaGetSymbolAddress((void**)&pQb,   g_qb);
    cudaGetSymbolAddress((void**)&pRawb, g_rawb);
    cudaGetSymbolAddress((void**)&pFFb,  g_ffb);

    auto gemm = [](const float* A, int lda, const float* W, const float* bias,
                   float* C, int ldc, int M, int N, int K, int relu) {
        dim3 grid(N / 64, (M + 63) / 64);
        gemm_k<<<grid, 256>>>(A, lda, W, bias, C, ldc, M, N, K, relu);
    };

    // ---- precompute ----
    bias_k<<<8, 256>>>(amask, pBias);
    // K/V of hidden_states for the 3 cross-attn modules (ctx, cross layer0, cross layer1)
    for (int m = 0; m < 3; m++) {
        const float* w = (m == 0) ? ctx_in_w : cross_in_w + (size_t)(m - 1) * 3 * cH * cH;
        const float* bb = (m == 0) ? ctx_in_b : cross_in_b + (size_t)(m - 1) * 3 * cH;
        gemm(hs, cH, w + (size_t)cH * cH,     bb + cH,     pK + (size_t)m * BSH, cH, cB * cS, cH, cH, 0);
        gemm(hs, cH, w + (size_t)2 * cH * cH, bb + 2 * cH, pV + (size_t)m * BSH, cH, cB * cS, cH, cH, 0);
    }

    // ---- generation loop ----
    for (int t = 0; t < cSTEPS; t++) {
        const int L = t + 1;
        const int M = cB * L;

        if (t == 0) embed0_k<<<8, 256>>>(sent, temb, pDec);
        else        argmax_embed_k<<<8, 256>>>(out + (size_t)(t - 1) * cV, cSTEPS * cV,
                                               tok_w, tok_b, pDec);

        // ctx attention for the new token -> cache slot t
        gemm(pDec, cH, ctx_in_w, ctx_in_b, pQnew, cH, cB, cH, cH, 0);
        cross_attn_k<<<dim3(cB * cNH, 1), 256>>>(pQnew, 1, pK, pV, pBias, pRaw1);
        gemm(pRaw1, cH, ctx_out_w, ctx_out_b, pXctx + (size_t)t * cH, cSTEPS * cH, cB, cH, cH, 0);
        // layer-0 self-attn QKV for the new token (input is step-invariant)
        gemm(pXctx + (size_t)t * cH, cSTEPS * cH, self_in_w, self_in_b,
             pQkv0 + (size_t)t * 3 * cH, cSTEPS * 3 * cH, cB, 3 * cH, cH, 0);

        // ---- layer 0 (all L positions) ----
        self_attn_k<<<cB * cNH, 256>>>(pQkv0, cSTEPS, L, pRawb, 0);
        gemm(pRawb, cH, self_out_w, self_out_b, pHb, cH, M, cH, cH, 0);
        add_ln_k<<<M, 256>>>(pXctx, cSTEPS, pHb, L, pX1, L, L,
                             norm_g + 0 * cH, norm_b + 0 * cH);
        gemm(pX1, cH, cross_in_w, cross_in_b, pQb, cH, M, cH, cH, 0);
        cross_attn_k<<<dim3(cB * cNH, (L + 7) / 8), 256>>>(pQb, L, pK + BSH, pV + BSH, pBias, pRawb);
        gemm(pRawb, cH, cross_out_w, cross_out_b, pHb, cH, M, cH, cH, 0);
        add_ln_k<<<M, 256>>>(pX1, L, pHb, L, pX1, L, L,
                             norm_g + 1 * cH, norm_b + 1 * cH);
        gemm(pX1, cH, ff1_w, ff1_b, pFFb, cFF, M, cFF, cH, 1);
        gemm(pFFb, cFF, ff2_w, ff2_b, pHb, cH, M, cH, cFF, 0);
        add_ln_k<<<M, 256>>>(pX1, L, pHb, L, pX1, L, L,
                             norm_g + 2 * cH, norm_b + 2 * cH);

        // ---- layer 1 (QKV for all L, rest last-position-only) ----
        gemm(pX1, cH, self_in_w + (size_t)3 * cH * cH, self_in_b + 3 * cH,
             pQkv1, 3 * cH, M, 3 * cH, cH, 0);
        self_attn_k<<<cB * cNH, 256>>>(pQkv1, L, L, pRaw1, 1);
        gemm(pRaw1, cH, self_out_w + (size_t)cH * cH, self_out_b + cH, pH8, cH, cB, cH, cH, 0);
        add_ln_k<<<cB, 256>>>(pX1 + (size_t)(L - 1) * cH, L, pH8, 1, pX8, 1, 1,
                              norm_g + 3 * cH, norm_b + 3 * cH);
        gemm(pX8, cH, cross_in_w + (size_t)3 * cH * cH, cross_in_b + 3 * cH, pQnew, cH, cB, cH, cH, 0);
        cross_attn_k<<<dim3(cB * cNH, 1), 256>>>(pQnew, 1, pK + 2 * BSH, pV + 2 * BSH, pBias, pRaw1);
        gemm(pRaw1, cH, cross_out_w + (size_t)cH * cH, cross_out_b + cH, pH8, cH, cB, cH, cH, 0);
        add_ln_k<<<cB, 256>>>(pX8, 1, pH8, 1, pX8, 1, 1,
                              norm_g + 4 * cH, norm_b + 4 * cH);
        gemm(pX8, cH, ff1_w + (size_t)cFF * cH, ff1_b + cFF, pFF8, cFF, cB, cFF, cH, 1);
        gemm(pFF8, cFF, ff2_w + (size_t)cH * cFF, ff2_b + cH, pH8, cH, cB, cH, cFF, 0);
        add_ln_k<<<cB, 256>>>(pX8, 1, pH8, 1, pX8, 1, 1,
                              norm_g + 5 * cH, norm_b + 5 * cH);

        // ---- logits for this step ----
        gemm(pX8, cH, out_w, out_b, out + (size_t)t * cV, cSTEPS * cV, cB, cV, cH, 0);
    }
}